// round 5
// baseline (speedup 1.0000x reference)
#include <cuda_runtime.h>

// ---------------------------------------------------------------------------
// GCN (3-layer, sum-aggregate) on GB300.
// Strategy: build CSR-by-dst once per launch (int atomics only), then each
// layer = dense GEMM (fp32, smem-tiled) + gather-aggregate over CSR
// (no float atomics; warp-per-node, 2 edges per iteration via half-warps).
// ---------------------------------------------------------------------------

#define MAX_N 100000
#define MAX_E 1600000

__device__ int   g_deg[MAX_N];
__device__ int   g_off[MAX_N + 1];
__device__ int   g_cur[MAX_N];
__device__ int   g_csr[MAX_E];
__device__ int   g_bsums[256];
__device__ float g_hw[(size_t)MAX_N * 64];
__device__ float g_h [(size_t)MAX_N * 64];

// ---------------- CSR build ----------------

__global__ void zero_deg(int n) {
    int i = blockIdx.x * blockDim.x + threadIdx.x;
    if (i < n) g_deg[i] = 0;
}

__global__ void hist_kernel(const int* __restrict__ dst, int e) {
    int i = blockIdx.x * blockDim.x + threadIdx.x;
    if (i < e) atomicAdd(&g_deg[dst[i]], 1);
}

// Exclusive scan over n_total = N+1 elements (element N has value 0).
__global__ void scan_block(int n_total) {
    __shared__ int wsum[32];
    int gid  = blockIdx.x * 1024 + threadIdx.x;
    int lane = threadIdx.x & 31;
    int wid  = threadIdx.x >> 5;
    int v = (gid < n_total - 1) ? g_deg[gid] : 0;

    int inc = v;
    #pragma unroll
    for (int d = 1; d < 32; d <<= 1) {
        int t = __shfl_up_sync(0xffffffffu, inc, d);
        if (lane >= d) inc += t;
    }
    if (lane == 31) wsum[wid] = inc;
    __syncthreads();
    if (wid == 0) {
        int s = wsum[lane];
        #pragma unroll
        for (int d = 1; d < 32; d <<= 1) {
            int t = __shfl_up_sync(0xffffffffu, s, d);
            if (lane >= d) s += t;
        }
        wsum[lane] = s;
    }
    __syncthreads();
    int add = wid ? wsum[wid - 1] : 0;
    if (gid < n_total) g_off[gid] = inc - v + add;
    if (threadIdx.x == 1023) g_bsums[blockIdx.x] = inc + add;
}

__global__ void scan_sums(int nb) {
    if (threadIdx.x == 0) {
        int run = 0;
        for (int b = 0; b < nb; b++) {
            int t = g_bsums[b];
            g_bsums[b] = run;
            run += t;
        }
    }
}

__global__ void scan_add(int n_total) {
    int gid = blockIdx.x * 1024 + threadIdx.x;
    if (gid < n_total) {
        int v = g_off[gid] + g_bsums[blockIdx.x];
        g_off[gid] = v;
        if (gid < n_total - 1) g_cur[gid] = v;
    }
}

__global__ void fill_csr(const int* __restrict__ src, const int* __restrict__ dst, int e) {
    int i = blockIdx.x * blockDim.x + threadIdx.x;
    if (i < e) {
        int p = atomicAdd(&g_cur[dst[i]], 1);
        g_csr[p] = src[i];
    }
}

// ---------------- dense GEMM: Y[n,64] = X[n,K] @ W[K,64] ----------------
// Block tile: 128 nodes x 64 ch, 256 threads, each thread 8 nodes x 4 ch.

template <int K>
__global__ void gemm64(const float* __restrict__ X, const float* __restrict__ W,
                       float* __restrict__ Y, int n) {
    extern __shared__ float smem[];
    float* xs = smem;                       // [128][K+1] (pad 1 -> conflict-free)
    float* ws = smem + 128 * (K + 1);       // [K][64]
    const int t    = threadIdx.x;
    const int base = blockIdx.x * 128;

    // load W (K*64 floats) as float4
    for (int i = t; i < K * 16; i += 256) {
        ((float4*)ws)[i] = ((const float4*)W)[i];
    }
    // load X tile (128 x K), zero-fill OOB rows
    for (int i = t; i < 128 * (K / 4); i += 256) {
        int r  = i / (K / 4);
        int c4 = i % (K / 4);
        int node = base + r;
        float4 v = make_float4(0.f, 0.f, 0.f, 0.f);
        if (node < n) v = ((const float4*)(X + (size_t)node * K))[c4];
        float* row = xs + r * (K + 1) + c4 * 4;
        row[0] = v.x; row[1] = v.y; row[2] = v.z; row[3] = v.w;
    }
    __syncthreads();

    const int tx = t & 15;       // channel group (4 ch)
    const int ty = t >> 4;       // node group (8 nodes)
    const int c0 = tx * 4;
    const float* xrow = xs + (ty * 8) * (K + 1);

    float acc[8][4];
    #pragma unroll
    for (int i = 0; i < 8; i++) {
        acc[i][0] = acc[i][1] = acc[i][2] = acc[i][3] = 0.f;
    }

    #pragma unroll 4
    for (int k = 0; k < K; k++) {
        float4 w4 = *(const float4*)(ws + k * 64 + c0);
        #pragma unroll
        for (int i = 0; i < 8; i++) {
            float xv = xrow[i * (K + 1) + k];
            acc[i][0] += xv * w4.x;
            acc[i][1] += xv * w4.y;
            acc[i][2] += xv * w4.z;
            acc[i][3] += xv * w4.w;
        }
    }

    #pragma unroll
    for (int i = 0; i < 8; i++) {
        int node = base + ty * 8 + i;
        if (node < n) {
            *(float4*)(Y + (size_t)node * 64 + c0) =
                make_float4(acc[i][0], acc[i][1], acc[i][2], acc[i][3]);
        }
    }
}

// ---------------- aggregation: out[n] = (relu?)(sum_{e in CSR[n]} hw[src_e] + b)
// One warp per node; half-warps process 2 edges/iter with float4 loads.

__global__ void agg64(const float* __restrict__ hw, const float* __restrict__ bias,
                      float* __restrict__ out, int n, int doRelu) {
    int warp = (blockIdx.x * blockDim.x + threadIdx.x) >> 5;
    if (warp >= n) return;
    const int lane = threadIdx.x & 31;
    const int half = lane >> 4;   // 0: even edges, 1: odd edges
    const int q    = lane & 15;   // float4 index within 64 channels

    int beg = g_off[warp];
    int end = g_off[warp + 1];

    float4 acc = make_float4(0.f, 0.f, 0.f, 0.f);
    int e = beg;
    for (; e + 1 < end; e += 2) {
        int src  = g_csr[e + half];
        float4 v = ((const float4*)(hw + (size_t)src * 64))[q];
        acc.x += v.x; acc.y += v.y; acc.z += v.z; acc.w += v.w;
    }
    if (e < end && half == 0) {   // odd trailing edge
        int src  = g_csr[e];
        float4 v = ((const float4*)(hw + (size_t)src * 64))[q];
        acc.x += v.x; acc.y += v.y; acc.z += v.z; acc.w += v.w;
    }

    acc.x += __shfl_xor_sync(0xffffffffu, acc.x, 16);
    acc.y += __shfl_xor_sync(0xffffffffu, acc.y, 16);
    acc.z += __shfl_xor_sync(0xffffffffu, acc.z, 16);
    acc.w += __shfl_xor_sync(0xffffffffu, acc.w, 16);

    if (half == 0) {
        float4 b = ((const float4*)bias)[q];
        acc.x += b.x; acc.y += b.y; acc.z += b.z; acc.w += b.w;
        if (doRelu) {
            acc.x = fmaxf(acc.x, 0.f); acc.y = fmaxf(acc.y, 0.f);
            acc.z = fmaxf(acc.z, 0.f); acc.w = fmaxf(acc.w, 0.f);
        }
        ((float4*)(out + (size_t)warp * 64))[q] = acc;
    }
}

// ---------------- launch ----------------

extern "C" void kernel_launch(void* const* d_in, const int* in_sizes, int n_in,
                              void* d_out, int out_size) {
    const float* x    = (const float*)d_in[0];
    const int*   esrc = (const int*)  d_in[1];
    const int*   edst = (const int*)  d_in[2];
    const float* W1   = (const float*)d_in[3];
    const float* b1   = (const float*)d_in[4];
    const float* W2   = (const float*)d_in[5];
    const float* b2   = (const float*)d_in[6];
    const float* W3   = (const float*)d_in[7];
    const float* b3   = (const float*)d_in[8];
    float* out = (float*)d_out;

    const int N = in_sizes[0] / 128;
    const int E = in_sizes[1];

    float *hw = nullptr, *h = nullptr;
    cudaGetSymbolAddress((void**)&hw, g_hw);
    cudaGetSymbolAddress((void**)&h,  g_h);

    const int smem1 = (128 * 129 + 128 * 64) * 4;   // K=128: 98816 B
    const int smem2 = (128 * 65  + 64 * 64)  * 4;   // K=64 : 49664 B
    cudaFuncSetAttribute(gemm64<128>, cudaFuncAttributeMaxDynamicSharedMemorySize, smem1);
    cudaFuncSetAttribute(gemm64<64>,  cudaFuncAttributeMaxDynamicSharedMemorySize, smem2);

    // --- CSR by destination ---
    zero_deg<<<(N + 255) / 256, 256>>>(N);
    hist_kernel<<<(E + 255) / 256, 256>>>(edst, E);
    const int ntot = N + 1;
    const int nb   = (ntot + 1023) / 1024;
    scan_block<<<nb, 1024>>>(ntot);
    scan_sums<<<1, 32>>>(nb);
    scan_add<<<nb, 1024>>>(ntot);
    fill_csr<<<(E + 255) / 256, 256>>>(esrc, edst, E);

    // --- 3 GCN layers ---
    const int gblocks = (N + 127) / 128;
    const int ablocks = (N + 7) / 8;    // 8 warps/block, warp per node

    gemm64<128><<<gblocks, 256, smem1>>>(x, W1, hw, N);
    agg64<<<ablocks, 256>>>(hw, b1, h, N, 1);

    gemm64<64><<<gblocks, 256, smem2>>>(h, W2, hw, N);
    agg64<<<ablocks, 256>>>(hw, b2, h, N, 1);

    gemm64<64><<<gblocks, 256, smem2>>>(h, W3, hw, N);
    agg64<<<ablocks, 256>>>(hw, b3, out, N, 0);
}